// round 1
// baseline (speedup 1.0000x reference)
#include <cuda_runtime.h>
#include <math.h>

#define NN 1500
#define NE 1200
#define NB 96
#define KC 375
#define KSPLIT 4
#define NSTEPS 60

// ---------------- static device buffers (no allocations allowed) ----------------
__device__ float2 d_WW[(size_t)NN * NN];          // [j][i] = (W[i][j], W[i][j]^2)  18MB
__device__ float  d_mean[NB * NN];                // [b][i]
__device__ float  d_rateA[NB * NN];               // ping
__device__ float  d_rateB[NB * NN];               // pong
__device__ float  d_pmu[KSPLIT * NB * NN];        // split-K partials of rate@W^T
__device__ float  d_ps2[KSPLIT * NB * NN];        // split-K partials of rate@(W^2)^T

__constant__ float c_contr[8] = {0.0f, 0.0432773f, 0.103411f, 0.186966f,
                                 0.303066f, 0.464386f, 0.68854f, 1.0f};

// ---------------- helpers ----------------
__device__ __forceinline__ float prefv(int n) {
    const float se = 179.99f / 1200.0f;
    const float si = 179.99f / 300.0f;
    return (n < NE) ? (float)n * se : (float)(n - NE) * si;
}

__device__ __forceinline__ unsigned long long pack2(float x, float y) {
    unsigned long long r;
    asm("mov.b64 %0, {%1,%2};" : "=l"(r) : "f"(x), "f"(y));
    return r;
}
__device__ __forceinline__ void unpack2(unsigned long long v, float& x, float& y) {
    asm("mov.b64 {%0,%1}, %2;" : "=f"(x), "=f"(y) : "l"(v));
}
// packed dual FMA: d.lo += a.lo*b.lo ; d.hi += a.hi*b.hi   (FFMA2, sm_103a)
__device__ __forceinline__ void fma2(unsigned long long& d, unsigned long long a,
                                     unsigned long long b) {
    asm("fma.rn.f32x2 %0, %1, %2, %0;" : "+l"(d) : "l"(a), "l"(b));
}

// ---------------- Ricciardi transfer ----------------
__device__ __forceinline__ float f_ricci(float x) {
    float z = x / (1.0f + x);
    float t = -z;
    float p = 0.14805913578876898f;
    p = p * t + 0.64290613877355551f;
    p = p * t + 1.0616084849547165f;
    p = p * t + 0.93524391761244940f;
    p = p * t + 0.62718906618071668f;
    p = p * t + 0.32171431660633076f;
    p = p * t + 0.32056016125642045f;
    p = p * t + 0.77373949685442023f;
    p = p * t + 0.22757881388024176f;
    p = p * t + 0.0f;
    return logf(2.0f * x + 1.0f) + p;
}

__device__ __forceinline__ float g_ricci(float x) {
    float z = x / (2.0f + x);
    float num = z * (3.5441754117462949f + z * (-7.0529131065835378f + z * (-56.532378057580381f
              + z * (279.56761105465944f + z * (-520.37554849441472f + z * (456.58245777026514f
              + z * (-155.73340457809226f)))))));
    float den = 1.0f + z * (-4.1357968834226053f + z * (-7.2984226138266743f + z * (98.656602235468327f
              + z * (-334.20436223415163f + z * (601.08633903294185f + z * (-599.58577549598340f
              + z * (277.18420330693891f + z * (-16.445022798669722f))))))));
    return num / den;
}

__device__ __forceinline__ float phi_f(float mu, float sig, float tau_ref) {
    const float tau = 0.01f;
    float xp = mu / sig;             // VR = 0
    float xm = (mu - 20.0f) / sig;   // VT = 20
    float r0;
    if (xm > 0.0f) {
        r0 = 1.0f / (f_ricci(xp) - f_ricci(xm));
    } else if (xp > 0.0f) {
        r0 = 1.0f / (f_ricci(xp) + expf(xm * xm) * g_ricci(-xm));
    } else {
        r0 = expf(-xm * xm - logf(g_ricci(-xm) - expf(xp * xp - xm * xm) * g_ricci(-xp)));
    }
    r0 = fmaxf(r0, 1e-30f);
    return 1.0f / (tau_ref + tau / r0);
}

// ---------------- setup kernels ----------------
__global__ void k_weights(const float* __restrict__ hyp, const float* __restrict__ rnd) {
    int tid = blockIdx.x * blockDim.x + threadIdx.x;
    if (tid >= NN * NN) return;
    int j = tid / NN;
    int i = tid - j * NN;                         // output layout [j][i] (coalesced write)
    int conn = (i >= NE ? 1 : 0) + 2 * (j >= NE ? 1 : 0);
    float J = hyp[conn], P = hyp[4 + conn], Wp = hyp[8 + conn];
    const float cd = 3.14159265358979323846f / 180.0f;
    float diff = fabsf(prefv(i) - prefv(j));
    float wden = 4.0f * (cd * Wp) * (cd * Wp);
    float z = expf((cosf(2.0f * cd * diff) - 1.0f) / wden);
    float x = 32.0f * (P * z - rnd[(size_t)i * NN + j]);
    float w = J / (1.0f + expf(-x));
    d_WW[tid] = make_float2(w, w * w);
}

__global__ void k_mean() {
    int tid = blockIdx.x * blockDim.x + threadIdx.x;
    if (tid >= NB * NN) return;
    int b = tid / NN;
    int n = tid - b * NN;
    int c = b / 12;
    int o = b - c * 12;
    const float cd = 3.14159265358979323846f / 180.0f;
    float dth = (float)o * 15.0f - prefv(n);
    const float wden = 4.0f * (cd * 30.0f) * (cd * 30.0f);
    float cg = expf((cosf(2.0f * cd * dth) - 1.0f) / wden);
    d_mean[tid] = c_contr[c] * 20.0f * cg;
}

// ---------------- step kernels ----------------
// Fused dual GEMM: mu_part[b,i] = sum_j rate[b,j]*W[i,j]; s2_part likewise with W^2.
// Grid: (6 neuron blocks of 256) x (6 batch blocks of 16) x (split-K 4 of 375)
__global__ __launch_bounds__(256) void k_accum(int rsel) {
    const float* __restrict__ rate = rsel ? d_rateB : d_rateA;
    const int i  = blockIdx.x * 256 + threadIdx.x;
    const int b0 = blockIdx.y * 16;
    const int j0 = blockIdx.z * KC;
    const int iC = (i < NN) ? i : (NN - 1);

    // rate tile as batch-pair-packed f32x2: rs[bp][jj] = (rate[b0+2bp][j], rate[b0+2bp+1][j])
    __shared__ unsigned long long rs[8][KC + 1];
    float* rsf = (float*)rs;
    for (int idx = threadIdx.x; idx < 16 * KC; idx += 256) {
        int bl = idx / KC;
        int jj = idx - bl * KC;
        float v = rate[(b0 + bl) * NN + j0 + jj];
        rsf[(((bl >> 1) * (KC + 1)) + jj) * 2 + (bl & 1)] = v;
    }
    __syncthreads();

    unsigned long long am[8], as[8];
#pragma unroll
    for (int p = 0; p < 8; p++) { am[p] = 0ULL; as[p] = 0ULL; }

    const float2* wp = d_WW + (size_t)j0 * NN + iC;
#pragma unroll 5
    for (int jj = 0; jj < KC; jj++) {
        float2 w = *wp;                 // (W[i][j], W2[i][j]) — one 8B L2-resident load
        wp += NN;
        unsigned long long wa = pack2(w.x, w.x);
        unsigned long long wb = pack2(w.y, w.y);
#pragma unroll
        for (int p = 0; p < 8; p++) {
            unsigned long long r = rs[p][jj];   // broadcast LDS.64
            fma2(am[p], r, wa);                 // mu accum for batch pair
            fma2(as[p], r, wb);                 // sigma^2 accum for batch pair
        }
    }

    if (i < NN) {
        const int kb = blockIdx.z * NB;
#pragma unroll
        for (int p = 0; p < 8; p++) {
            float lo, hi;
            unpack2(am[p], lo, hi);
            d_pmu[(kb + b0 + 2 * p) * NN + i]     = lo;
            d_pmu[(kb + b0 + 2 * p + 1) * NN + i] = hi;
            unpack2(as[p], lo, hi);
            d_ps2[(kb + b0 + 2 * p) * NN + i]     = lo;
            d_ps2[(kb + b0 + 2 * p + 1) * NN + i] = hi;
        }
    }
}

// Reduce split-K partials, apply phi, Euler update.
__global__ void k_update(int rsel_in, int rsel_out, int first) {
    int tid = blockIdx.x * blockDim.x + threadIdx.x;
    if (tid >= NB * NN) return;
    int b = tid / NN;
    int i = tid - b * NN;

    float ms = 0.0f, ss = 0.0f, rold = 0.0f;
    if (!first) {
        const float* rin = rsel_in ? d_rateB : d_rateA;
#pragma unroll
        for (int k = 0; k < KSPLIT; k++) {
            ms += d_pmu[(k * NB + b) * NN + i];
            ss += d_ps2[(k * NB + b) * NN + i];
        }
        rold = rin[tid];
    }
    float mu  = 0.01f * ms + d_mean[tid];
    float sig = sqrtf(0.01f * ss + 25.0f);     // SIG_EXT^2 = 25
    float tr = (i < NE) ? 0.005f : 0.001f;
    float aT = (i < NE) ? 0.1f : 0.2f;         // DT * T_inv
    float p = phi_f(mu, sig, tr);
    float* rout = rsel_out ? d_rateB : d_rateA;
    rout[tid] = rold + aT * (p - rold);
}

// out[n, c, o] = rate[c*12+o, n]
__global__ void k_out(int rsel, float* __restrict__ out) {
    int tid = blockIdx.x * blockDim.x + threadIdx.x;
    if (tid >= NB * NN) return;
    int n = tid / NB;
    int b = tid - n * NB;
    const float* r = rsel ? d_rateB : d_rateA;
    out[tid] = r[b * NN + n];
}

// ---------------- launch ----------------
extern "C" void kernel_launch(void* const* d_in, const int* in_sizes, int n_in,
                              void* d_out, int out_size) {
    const float* hyp = (const float*)d_in[0];
    const float* rnd = (const float*)d_in[1];
    float* out = (float*)d_out;

    k_weights<<<(NN * NN + 255) / 256, 256>>>(hyp, rnd);
    k_mean<<<(NB * NN + 255) / 256, 256>>>();

    const int UB = (NB * NN + 255) / 256;
    // step 1: rate starts at zero -> mu = mean, sig = 5; write into B
    k_update<<<UB, 256>>>(0, 1, 1);
    int cur = 1;
    for (int s = 1; s < NSTEPS; s++) {
        k_accum<<<dim3(6, 6, KSPLIT), 256>>>(cur);
        k_update<<<UB, 256>>>(cur, cur ^ 1, 0);
        cur ^= 1;
    }
    k_out<<<(NB * NN + 255) / 256, 256>>>(cur, out);
}

// round 2
// speedup vs baseline: 1.2380x; 1.2380x over previous
#include <cuda_runtime.h>
#include <math.h>

#define NN 1500
#define NE 1200
#define NB 96
#define KC 125
#define KSPLIT 12
#define NSTEPS 60

// ---------------- static device buffers (no allocations allowed) ----------------
__device__ float2 d_WW[(size_t)NN * NN];          // [j][i] = (W[i][j], W[i][j]^2)  18MB
__device__ float  d_mean[NB * NN];                // [b][i]
__device__ float  d_rateA[NB * NN];               // ping
__device__ float  d_rateB[NB * NN];               // pong
__device__ float  d_pmu[KSPLIT * NB * NN];        // split-K partials of rate@W^T
__device__ float  d_ps2[KSPLIT * NB * NN];        // split-K partials of rate@(W^2)^T

__constant__ float c_contr[8] = {0.0f, 0.0432773f, 0.103411f, 0.186966f,
                                 0.303066f, 0.464386f, 0.68854f, 1.0f};

// ---------------- helpers ----------------
__device__ __forceinline__ float prefv(int n) {
    const float se = 179.99f / 1200.0f;
    const float si = 179.99f / 300.0f;
    return (n < NE) ? (float)n * se : (float)(n - NE) * si;
}

__device__ __forceinline__ unsigned long long pack2(float x, float y) {
    unsigned long long r;
    asm("mov.b64 %0, {%1,%2};" : "=l"(r) : "f"(x), "f"(y));
    return r;
}
__device__ __forceinline__ void unpack2(unsigned long long v, float& x, float& y) {
    asm("mov.b64 {%0,%1}, %2;" : "=f"(x), "=f"(y) : "l"(v));
}
// packed dual FMA: d.lo += a.lo*b.lo ; d.hi += a.hi*b.hi   (FFMA2, sm_103a)
__device__ __forceinline__ void fma2(unsigned long long& d, unsigned long long a,
                                     unsigned long long b) {
    asm("fma.rn.f32x2 %0, %1, %2, %0;" : "+l"(d) : "l"(a), "l"(b));
}

// ---------------- Ricciardi transfer ----------------
__device__ __forceinline__ float f_ricci(float x) {
    float z = x / (1.0f + x);
    float t = -z;
    float p = 0.14805913578876898f;
    p = p * t + 0.64290613877355551f;
    p = p * t + 1.0616084849547165f;
    p = p * t + 0.93524391761244940f;
    p = p * t + 0.62718906618071668f;
    p = p * t + 0.32171431660633076f;
    p = p * t + 0.32056016125642045f;
    p = p * t + 0.77373949685442023f;
    p = p * t + 0.22757881388024176f;
    p = p * t + 0.0f;
    return logf(2.0f * x + 1.0f) + p;
}

__device__ __forceinline__ float g_ricci(float x) {
    float z = x / (2.0f + x);
    float num = z * (3.5441754117462949f + z * (-7.0529131065835378f + z * (-56.532378057580381f
              + z * (279.56761105465944f + z * (-520.37554849441472f + z * (456.58245777026514f
              + z * (-155.73340457809226f)))))));
    float den = 1.0f + z * (-4.1357968834226053f + z * (-7.2984226138266743f + z * (98.656602235468327f
              + z * (-334.20436223415163f + z * (601.08633903294185f + z * (-599.58577549598340f
              + z * (277.18420330693891f + z * (-16.445022798669722f))))))));
    return num / den;
}

__device__ __forceinline__ float phi_f(float mu, float sig, float tau_ref) {
    const float tau = 0.01f;
    float xp = mu / sig;             // VR = 0
    float xm = (mu - 20.0f) / sig;   // VT = 20
    float r0;
    if (xm > 0.0f) {
        r0 = 1.0f / (f_ricci(xp) - f_ricci(xm));
    } else if (xp > 0.0f) {
        r0 = 1.0f / (f_ricci(xp) + expf(xm * xm) * g_ricci(-xm));
    } else {
        r0 = expf(-xm * xm - logf(g_ricci(-xm) - expf(xp * xp - xm * xm) * g_ricci(-xp)));
    }
    r0 = fmaxf(r0, 1e-30f);
    return 1.0f / (tau_ref + tau / r0);
}

// ---------------- setup kernels ----------------
__global__ void k_weights(const float* __restrict__ hyp, const float* __restrict__ rnd) {
    int tid = blockIdx.x * blockDim.x + threadIdx.x;
    if (tid >= NN * NN) return;
    int j = tid / NN;
    int i = tid - j * NN;                         // output layout [j][i] (coalesced write)
    int conn = (i >= NE ? 1 : 0) + 2 * (j >= NE ? 1 : 0);
    float J = hyp[conn], P = hyp[4 + conn], Wp = hyp[8 + conn];
    const float cd = 3.14159265358979323846f / 180.0f;
    float diff = fabsf(prefv(i) - prefv(j));
    float wden = 4.0f * (cd * Wp) * (cd * Wp);
    float z = expf((cosf(2.0f * cd * diff) - 1.0f) / wden);
    float x = 32.0f * (P * z - rnd[(size_t)i * NN + j]);
    float w = J / (1.0f + expf(-x));
    d_WW[tid] = make_float2(w, w * w);
}

__global__ void k_mean() {
    int tid = blockIdx.x * blockDim.x + threadIdx.x;
    if (tid >= NB * NN) return;
    int b = tid / NN;
    int n = tid - b * NN;
    int c = b / 12;
    int o = b - c * 12;
    const float cd = 3.14159265358979323846f / 180.0f;
    float dth = (float)o * 15.0f - prefv(n);
    const float wden = 4.0f * (cd * 30.0f) * (cd * 30.0f);
    float cg = expf((cosf(2.0f * cd * dth) - 1.0f) / wden);
    d_mean[tid] = c_contr[c] * 20.0f * cg;
}

// ---------------- step kernels ----------------
// Fused dual GEMM: mu_part[b,i] = sum_j rate[b,j]*W[i,j]; s2_part likewise with W^2.
// Grid: (6 neuron blocks of 256) x (6 batch blocks of 16) x (split-K 12 of 125)
// 432 CTAs -> 3 CTAs/SM (occ 37.5%), explicit 5-deep weight prefetch for MLP.
__global__ __launch_bounds__(256, 3) void k_accum(int rsel) {
    const float* __restrict__ rate = rsel ? d_rateB : d_rateA;
    const int i  = blockIdx.x * 256 + threadIdx.x;
    const int b0 = blockIdx.y * 16;
    const int j0 = blockIdx.z * KC;
    const int iC = (i < NN) ? i : (NN - 1);

    // rate tile as batch-pair-packed f32x2: rs[bp][jj] = (rate[b0+2bp][j], rate[b0+2bp+1][j])
    __shared__ unsigned long long rs[8][KC + 1];
    float* rsf = (float*)rs;
    for (int idx = threadIdx.x; idx < 16 * KC; idx += 256) {
        int bl = idx / KC;
        int jj = idx - bl * KC;
        float v = rate[(b0 + bl) * NN + j0 + jj];
        rsf[(((bl >> 1) * (KC + 1)) + jj) * 2 + (bl & 1)] = v;
    }
    __syncthreads();

    unsigned long long am[8], as[8];
#pragma unroll
    for (int p = 0; p < 8; p++) { am[p] = 0ULL; as[p] = 0ULL; }

    const float2* wp = d_WW + (size_t)j0 * NN + iC;

    // software pipeline: 5 weight loads in flight per warp
    float2 wbuf[5];
#pragma unroll
    for (int u = 0; u < 5; u++) wbuf[u] = wp[(size_t)u * NN];
    wp += (size_t)5 * NN;

    for (int base = 0; base < KC; base += 5) {     // KC = 125 = 25 * 5
        float2 cur[5];
#pragma unroll
        for (int u = 0; u < 5; u++) cur[u] = wbuf[u];
        if (base + 5 < KC) {
#pragma unroll
            for (int u = 0; u < 5; u++) wbuf[u] = wp[(size_t)u * NN];
            wp += (size_t)5 * NN;
        }
#pragma unroll
        for (int u = 0; u < 5; u++) {
            unsigned long long wa = pack2(cur[u].x, cur[u].x);
            unsigned long long wb = pack2(cur[u].y, cur[u].y);
#pragma unroll
            for (int p = 0; p < 8; p++) {
                unsigned long long r = rs[p][base + u];   // broadcast LDS.64
                fma2(am[p], r, wa);                       // mu accum for batch pair
                fma2(as[p], r, wb);                       // sigma^2 accum for batch pair
            }
        }
    }

    if (i < NN) {
        const int kb = blockIdx.z * NB;
#pragma unroll
        for (int p = 0; p < 8; p++) {
            float lo, hi;
            unpack2(am[p], lo, hi);
            d_pmu[(kb + b0 + 2 * p) * NN + i]     = lo;
            d_pmu[(kb + b0 + 2 * p + 1) * NN + i] = hi;
            unpack2(as[p], lo, hi);
            d_ps2[(kb + b0 + 2 * p) * NN + i]     = lo;
            d_ps2[(kb + b0 + 2 * p + 1) * NN + i] = hi;
        }
    }
}

// Reduce split-K partials, apply phi, Euler update.
__global__ void k_update(int rsel_in, int rsel_out, int first) {
    int tid = blockIdx.x * blockDim.x + threadIdx.x;
    if (tid >= NB * NN) return;
    int b = tid / NN;
    int i = tid - b * NN;

    float ms = 0.0f, ss = 0.0f, rold = 0.0f;
    if (!first) {
        const float* rin = rsel_in ? d_rateB : d_rateA;
#pragma unroll
        for (int k = 0; k < KSPLIT; k++) {
            ms += d_pmu[(k * NB + b) * NN + i];
            ss += d_ps2[(k * NB + b) * NN + i];
        }
        rold = rin[tid];
    }
    float mu  = 0.01f * ms + d_mean[tid];
    float sig = sqrtf(0.01f * ss + 25.0f);     // SIG_EXT^2 = 25
    float tr = (i < NE) ? 0.005f : 0.001f;
    float aT = (i < NE) ? 0.1f : 0.2f;         // DT * T_inv
    float p = phi_f(mu, sig, tr);
    float* rout = rsel_out ? d_rateB : d_rateA;
    rout[tid] = rold + aT * (p - rold);
}

// out[n, c, o] = rate[c*12+o, n]
__global__ void k_out(int rsel, float* __restrict__ out) {
    int tid = blockIdx.x * blockDim.x + threadIdx.x;
    if (tid >= NB * NN) return;
    int n = tid / NB;
    int b = tid - n * NB;
    const float* r = rsel ? d_rateB : d_rateA;
    out[tid] = r[b * NN + n];
}

// ---------------- launch ----------------
extern "C" void kernel_launch(void* const* d_in, const int* in_sizes, int n_in,
                              void* d_out, int out_size) {
    const float* hyp = (const float*)d_in[0];
    const float* rnd = (const float*)d_in[1];
    float* out = (float*)d_out;

    k_weights<<<(NN * NN + 255) / 256, 256>>>(hyp, rnd);
    k_mean<<<(NB * NN + 255) / 256, 256>>>();

    const int UB = (NB * NN + 255) / 256;
    // step 1: rate starts at zero -> mu = mean, sig = 5; write into B
    k_update<<<UB, 256>>>(0, 1, 1);
    int cur = 1;
    for (int s = 1; s < NSTEPS; s++) {
        k_accum<<<dim3(6, 6, KSPLIT), 256>>>(cur);
        k_update<<<UB, 256>>>(cur, cur ^ 1, 0);
        cur ^= 1;
    }
    k_out<<<(NB * NN + 255) / 256, 256>>>(cur, out);
}